// round 11
// baseline (speedup 1.0000x reference)
#include <cuda_runtime.h>
#include <math.h>

// Problem constants
#define B_   4
#define C_   192
#define HWD  192          // spatial H = W = 192
#define HW_  36864        // 192*192
#define CH2  384          // 2*C
#define HEADS 6
#define HD    32          // head dim (C/heads)
#define NSPLIT 18         // split-K chunks for Gram matrix (36864/18 = 2048)

// ---------------- scratch (static device globals; no allocation) -------------
__device__ float g_kv1[(size_t)B_ * CH2 * HW_];   // 1x1 conv output (pre-depthwise)
__device__ float g_kv2[(size_t)B_ * CH2 * HW_];   // k (ch 0..191) | v (ch 192..383)
__device__ float g_q  [(size_t)B_ * C_  * HW_];   // q = 3x3 conv output
__device__ float g_Aq [1728 * C_];                // q weights, K-major [k][m], k=(rs)*192+ic
__device__ float g_Akv[C_ * CH2];                 // kv 1x1 weights, K-major [ic][oc]
__device__ float g_part[24 * NSPLIT * 1024];      // Gram partials [bh][split][32][32]
__device__ float g_psq [24 * NSPLIT * 32];        // sum(q^2) partials
__device__ float g_psk [24 * NSPLIT * 32];        // sum(k^2) partials
__device__ float g_M   [B_ * C_ * C_];            // fused (proj @ attn) matrix, K-major [b][d][oc]

// ---------------- weight reordering ------------------------------------------
__global__ void prep_weights(const float* __restrict__ qw,
                             const float* __restrict__ kvw) {
    int idx = blockIdx.x * blockDim.x + threadIdx.x;
    if (idx < 1728 * C_) {
        int k = idx / C_, m = idx % C_;          // k = rs*192 + ic
        int rs = k / C_, ic = k % C_;
        // qw layout OIHW: [oc][ic][3][3]
        g_Aq[idx] = qw[(m * C_ + ic) * 9 + rs];
    }
    if (idx < C_ * CH2) {
        int ic = idx / CH2, oc = idx % CH2;
        g_Akv[idx] = kvw[oc * C_ + ic];          // kvw [384][192][1][1]
    }
}

// ---------------- SGEMM 96x128x8, 6x8 microtile, fp32 ------------------------
// C[m,n] = sum_k A[k][m] * B[k][n];  A is K-major (lda = M).
// Plain mode: B[k][n] = Bsrc[k*HW_ + n]   (row stride HW_)
// Conv mode : implicit 3x3 SAME conv im2col of x: k = rs*192+ic,
//             B[k][n] = x[ic][h+dr][w+dc] with zero padding.
// All dims are exact multiples of tiles -> no guards anywhere.
template<bool CONV>
__global__ void __launch_bounds__(256)
sgemm96(const float* __restrict__ A, long long A_bs,
        const float* __restrict__ Bsrc, long long B_bs,
        float* __restrict__ Cdst, long long C_bs,
        int M, int K) {
    const int b  = blockIdx.z;
    const int n0 = blockIdx.x * 128;
    const int m0 = blockIdx.y * 96;
    const float* Ab = A    + (size_t)b * A_bs;
    const float* Bb = Bsrc + (size_t)b * B_bs;
    float*       Cb = Cdst + (size_t)b * C_bs;

    __shared__ float As[8][96];
    __shared__ float Bs[8][128];

    const int tid = threadIdx.x;
    const int ty = tid >> 4, tx = tid & 15;      // 16x16 thread grid
    const int bk = tid >> 5;                     // 0..7   (B-tile row)
    const int bn = (tid & 31) * 4;               // 0..124 (B-tile col, x4)

    float acc[6][8];
#pragma unroll
    for (int r = 0; r < 6; r++)
#pragma unroll
        for (int c = 0; c < 8; c++) acc[r][c] = 0.f;

    for (int k0 = 0; k0 < K; k0 += 8) {
        // load A tile: 768 elems / 256 threads = 3 each
#pragma unroll
        for (int i = 0; i < 3; i++) {
            int e = tid + i * 256;
            int kk = e / 96, mm = e % 96;
            As[kk][mm] = Ab[(size_t)(k0 + kk) * M + m0 + mm];
        }
        // load B tile: 1024 elems / 256 threads = 4 each
        if (!CONV) {
            float4 v = *(const float4*)(Bb + (size_t)(k0 + bk) * HW_ + n0 + bn);
            *(float4*)&Bs[bk][bn] = v;
        } else {
            int gk = k0 + bk;
            int rs = gk / C_;
            int ic = gk - rs * C_;
            int dr = rs / 3 - 1, dc = rs % 3 - 1;
            const float* xp = Bb + (size_t)ic * HW_;
#pragma unroll
            for (int i = 0; i < 4; i++) {
                int n  = n0 + bn + i;
                int h  = n / HWD, w = n - h * HWD;
                int hh = h + dr,  ww = w + dc;
                float v = 0.f;
                if ((unsigned)hh < (unsigned)HWD && (unsigned)ww < (unsigned)HWD)
                    v = xp[hh * HWD + ww];
                Bs[bk][bn + i] = v;
            }
        }
        __syncthreads();
#pragma unroll
        for (int p = 0; p < 8; p++) {
            float a[6], bb[8];
#pragma unroll
            for (int r = 0; r < 6; r++) a[r] = As[p][ty * 6 + r];
#pragma unroll
            for (int c = 0; c < 8; c++) bb[c] = Bs[p][tx * 8 + c];
#pragma unroll
            for (int r = 0; r < 6; r++)
#pragma unroll
                for (int c = 0; c < 8; c++) acc[r][c] += a[r] * bb[c];
        }
        __syncthreads();
    }
#pragma unroll
    for (int r = 0; r < 6; r++) {
        float* cp = Cb + (size_t)(m0 + ty * 6 + r) * HW_ + n0 + tx * 8;
        *(float4*)cp       = make_float4(acc[r][0], acc[r][1], acc[r][2], acc[r][3]);
        *((float4*)cp + 1) = make_float4(acc[r][4], acc[r][5], acc[r][6], acc[r][7]);
    }
}

// ---------------- depthwise 3x3 SAME, groups = 384 ---------------------------
__global__ void dwconv3x3(const float* __restrict__ w) {
    size_t idx = (size_t)blockIdx.x * 256 + threadIdx.x;
    int pix = (int)(idx % HW_);
    size_t bc = idx / HW_;                 // b*384 + ch
    int ch = (int)(bc % CH2);
    int h = pix / HWD, x_ = pix - h * HWD;
    const float* wp = w + ch * 9;
    const float* ip = g_kv1 + bc * HW_;
    float s = 0.f;
#pragma unroll
    for (int r = 0; r < 3; r++) {
        int hh = h + r - 1;
        if ((unsigned)hh < (unsigned)HWD) {
#pragma unroll
            for (int c2 = 0; c2 < 3; c2++) {
                int ww = x_ + c2 - 1;
                if ((unsigned)ww < (unsigned)HWD)
                    s += wp[r * 3 + c2] * ip[hh * HWD + ww];
            }
        }
    }
    g_kv2[idx] = s;
}

// ---------------- Gram matrix q·kᵀ + fused sum-of-squares (split-K) ----------
// grid (24, NSPLIT), block 1024 = 32x32. Thread (i=tid/32, j=tid%32)
// accumulates dot(q_i, k_j) over a 2048-column chunk; warp i also reduces
// sum(q_i^2), sum(k_i^2) over its chunk. Deterministic (no atomics).
__global__ void __launch_bounds__(1024)
gram_partial() {
    int bh = blockIdx.x, s = blockIdx.y;
    int b = bh / HEADS, h = bh % HEADS;
    int row = threadIdx.x >> 5;          // i / warp id
    int col = threadIdx.x & 31;          // j / lane id
    __shared__ float qs[32][33], ks[32][33];

    const float* qrow = g_q   + ((size_t)b * C_  + h * HD + row) * HW_;
    const float* krow = g_kv2 + ((size_t)b * CH2 + h * HD + row) * HW_;

    float acc = 0.f, aq = 0.f, ak = 0.f;
    int nbase = s * 2048;
    for (int it = 0; it < 64; it++) {
        int n = nbase + it * 32 + col;
        float qv = qrow[n];
        float kv = krow[n];
        qs[row][col] = qv;
        ks[row][col] = kv;
        aq += qv * qv;
        ak += kv * kv;
        __syncthreads();
#pragma unroll
        for (int t = 0; t < 32; t++)
            acc += qs[row][t] * ks[col][t];
        __syncthreads();
    }
    g_part[((size_t)(bh * NSPLIT + s)) * 1024 + row * 32 + col] = acc;
#pragma unroll
    for (int off = 16; off; off >>= 1) {
        aq += __shfl_xor_sync(0xffffffffu, aq, off);
        ak += __shfl_xor_sync(0xffffffffu, ak, off);
    }
    if (col == 0) {
        g_psq[(bh * NSPLIT + s) * 32 + row] = aq;
        g_psk[(bh * NSPLIT + s) * 32 + row] = ak;
    }
}

// ---------------- softmax + fused (proj @ attn) matrix build -----------------
__global__ void __launch_bounds__(256)
softmax_buildM(const float* __restrict__ proj_w,
               const float* __restrict__ temperature) {
    int bh = blockIdx.x;
    int b = bh / HEADS, h = bh % HEADS;
    int tid = threadIdx.x;
    __shared__ float att[32][32];
    __shared__ float invq[32], invk[32];

    // reduce Gram partials
    for (int e = tid; e < 1024; e += 256) {
        float s = 0.f;
        for (int p = 0; p < NSPLIT; p++)
            s += g_part[((size_t)(bh * NSPLIT + p)) * 1024 + e];
        att[e >> 5][e & 31] = s;
    }
    if (tid < 32) {
        float sq = 0.f, sk = 0.f;
        for (int p = 0; p < NSPLIT; p++) {
            sq += g_psq[(bh * NSPLIT + p) * 32 + tid];
            sk += g_psk[(bh * NSPLIT + p) * 32 + tid];
        }
        invq[tid] = 1.f / fmaxf(sqrtf(sq), 1e-12f);
        invk[tid] = 1.f / fmaxf(sqrtf(sk), 1e-12f);
    }
    __syncthreads();

    float temp = temperature[h];
    for (int e = tid; e < 1024; e += 256) {
        int i = e >> 5, j = e & 31;
        att[i][j] = att[i][j] * invq[i] * invk[j] * temp;
    }
    __syncthreads();

    if (tid < 32) {                       // row-wise softmax over j
        int i = tid;
        float mx = -1e30f;
        for (int j = 0; j < 32; j++) mx = fmaxf(mx, att[i][j]);
        float sum = 0.f;
        for (int j = 0; j < 32; j++) { float e2 = __expf(att[i][j] - mx); att[i][j] = e2; sum += e2; }
        float inv = 1.f / sum;
        for (int j = 0; j < 32; j++) att[i][j] *= inv;
    }
    __syncthreads();

    // M[oc, d] = sum_c proj[oc, hbase+c] * att[c][d]   (stored K-major: [d][oc])
    for (int e = tid; e < C_ * HD; e += 256) {
        int oc = e >> 5;      // 0..191
        int d  = e & 31;
        float s = 0.f;
#pragma unroll
        for (int c = 0; c < 32; c++)
            s += proj_w[oc * C_ + h * HD + c] * att[c][d];
        g_M[((size_t)b * C_ + h * HD + d) * C_ + oc] = s;
    }
}

// ---------------- launch ------------------------------------------------------
extern "C" void kernel_launch(void* const* d_in, const int* in_sizes, int n_in,
                              void* d_out, int out_size) {
    const float* x      = (const float*)d_in[0];
    const float* y      = (const float*)d_in[1];
    const float* q_w    = (const float*)d_in[2];
    const float* kv_w   = (const float*)d_in[3];
    const float* kvdw_w = (const float*)d_in[4];
    const float* proj_w = (const float*)d_in[5];
    const float* temp   = (const float*)d_in[6];
    float* out = (float*)d_out;

    float *pAq, *pAkv, *pM, *pkv1, *pkv2, *pq;
    cudaGetSymbolAddress((void**)&pAq,  g_Aq);
    cudaGetSymbolAddress((void**)&pAkv, g_Akv);
    cudaGetSymbolAddress((void**)&pM,   g_M);
    cudaGetSymbolAddress((void**)&pkv1, g_kv1);
    cudaGetSymbolAddress((void**)&pkv2, g_kv2);
    cudaGetSymbolAddress((void**)&pq,   g_q);

    // 1. weight reorder
    prep_weights<<<(1728 * C_ + 255) / 256, 256>>>(q_w, kv_w);

    // 2. kv = 1x1 conv(y): C[384,36864] = Akv^T[384x192] * y  (per batch)
    sgemm96<false><<<dim3(HW_ / 128, CH2 / 96, B_), 256>>>(
        pAkv, 0LL, y, (long long)C_ * HW_, pkv1, (long long)CH2 * HW_, CH2, C_);

    // 3. depthwise 3x3
    dwconv3x3<<<(unsigned)(((size_t)B_ * CH2 * HW_) / 256), 256>>>(kvdw_w);

    // 4. q = 3x3 conv(x), implicit GEMM K=1728
    sgemm96<true><<<dim3(HW_ / 128, C_ / 96, B_), 256>>>(
        pAq, 0LL, x, (long long)C_ * HW_, pq, (long long)C_ * HW_, C_, 1728);

    // 5. Gram matrix + sumsq (split-K, deterministic)
    gram_partial<<<dim3(B_ * HEADS, NSPLIT), 1024>>>();

    // 6. softmax + fused proj@attn matrix
    softmax_buildM<<<B_ * HEADS, 256>>>(proj_w, temp);

    // 7. out = M @ v   (fuses attn@v and the 1x1 projection)
    sgemm96<false><<<dim3(HW_ / 128, C_ / 96, B_), 256>>>(
        pM, (long long)C_ * C_,
        pkv2 + (size_t)C_ * HW_, (long long)CH2 * HW_,   // v = channels 192..383
        out, (long long)C_ * HW_, C_, C_);
}

// round 12
// speedup vs baseline: 1.1302x; 1.1302x over previous
#include <cuda_runtime.h>
#include <math.h>

// Problem constants
#define B_   4
#define C_   192
#define HWD  192          // spatial H = W = 192
#define HW_  36864        // 192*192
#define CH2  384          // 2*C
#define HEADS 6
#define HD    32          // head dim (C/heads)
#define NSPLIT 18         // split-K chunks for Gram matrix (36864/18 = 2048)
#define KT   16           // GEMM k-tile

typedef unsigned long long ull;

// ---------------- scratch (static device globals; no allocation) -------------
__device__ float g_kv1[(size_t)B_ * CH2 * HW_];   // 1x1 conv output (pre-depthwise)
__device__ float g_kv2[(size_t)B_ * CH2 * HW_];   // k (ch 0..191) | v (ch 192..383)
__device__ float g_q  [(size_t)B_ * C_  * HW_];   // q = 3x3 conv output
__device__ float g_Aq [1728 * C_];                // q weights, K-major [k][m], k=rs*192+ic
__device__ float g_Akv[C_ * CH2];                 // kv 1x1 weights, K-major [ic][oc]
__device__ float g_part[24 * NSPLIT * 1024];      // Gram partials [bh][split][32][32]
__device__ float g_psq [24 * NSPLIT * 32];        // sum(q^2) partials
__device__ float g_psk [24 * NSPLIT * 32];        // sum(k^2) partials
__device__ float g_M   [B_ * C_ * C_];            // fused (proj @ attn), K-major [b][d][oc]

// ---------------- packed f32x2 helpers ----------------------------------------
__device__ __forceinline__ ull pack2(float a) {
    ull r;
    asm("mov.b64 %0, {%1, %1};" : "=l"(r) : "r"(__float_as_uint(a)));
    return r;
}
__device__ __forceinline__ void ffma2(ull& acc, ull a, ull b) {
    asm("fma.rn.f32x2 %0, %1, %2, %0;" : "+l"(acc) : "l"(a), "l"(b));
}

// ---------------- weight reordering ------------------------------------------
__global__ void prep_weights(const float* __restrict__ qw,
                             const float* __restrict__ kvw) {
    int idx = blockIdx.x * blockDim.x + threadIdx.x;
    if (idx < 1728 * C_) {
        int k = idx / C_, m = idx % C_;          // k = rs*192 + ic
        int rs = k / C_, ic = k % C_;
        g_Aq[idx] = qw[(m * C_ + ic) * 9 + rs];  // qw OIHW [oc][ic][3][3]
    }
    if (idx < C_ * CH2) {
        int ic = idx / CH2, oc = idx % CH2;
        g_Akv[idx] = kvw[oc * C_ + ic];          // kvw [384][192][1][1]
    }
}

// ---------------- SGEMM 96x128xKT, 6x8 microtile, packed f32x2 ---------------
// C[m,n] = sum_k A[k][m] * B[k][n];  A is K-major (lda = M).
// Plain: B[k][n] = Bsrc[k*HW_ + n].
// Conv : implicit 3x3 SAME im2col of x: k = rs*192+ic,
//        B[k][n] = x[ic][h+dr][w+dc] with zero padding.
template<bool CONV>
__global__ void __launch_bounds__(256)
sgemm96(const float* __restrict__ A, long long A_bs,
        const float* __restrict__ Bsrc, long long B_bs,
        float* __restrict__ Cdst, long long C_bs,
        int M, int K) {
    const int b  = blockIdx.z;
    const int n0 = blockIdx.x * 128;
    const int m0 = blockIdx.y * 96;
    const float* Ab = A    + (size_t)b * A_bs;
    const float* Bb = Bsrc + (size_t)b * B_bs;
    float*       Cb = Cdst + (size_t)b * C_bs;

    __shared__ __align__(16) float As[KT][96];
    __shared__ __align__(16) float Bs[KT][128];

    const int tid  = threadIdx.x;
    const int ty   = tid >> 4, tx = tid & 15;    // 16x16 thread grid
    const int bk   = tid >> 5;                   // 0..7 (B-tile k row, +8 for 2nd)
    const int lane = tid & 31;

    ull acc[6][4];                               // 6 m-rows x 4 n-pairs
#pragma unroll
    for (int r = 0; r < 6; r++)
#pragma unroll
        for (int j = 0; j < 4; j++) acc[r][j] = 0ULL;

    for (int k0 = 0; k0 < K; k0 += KT) {
        // ---- A tile: 96*KT = 1536 elems / 256 thr = 6 each
#pragma unroll
        for (int i = 0; i < 6; i++) {
            int e = tid + i * 256;
            int kk = e / 96, mm = e - kk * 96;
            As[kk][mm] = Ab[(size_t)(k0 + kk) * M + m0 + mm];
        }
        // ---- B tile: 128*KT = 2048 elems / 256 thr = 8 each
        if (!CONV) {
#pragma unroll
            for (int i2 = 0; i2 < 2; i2++) {
                int kk = bk + 8 * i2;
                float4 v = *(const float4*)(Bb + (size_t)(k0 + kk) * HW_ + n0 + lane * 4);
                *(float4*)&Bs[kk][lane * 4] = v;
            }
        } else {
#pragma unroll
            for (int i2 = 0; i2 < 2; i2++) {
                int kk = bk + 8 * i2;
                int gk = k0 + kk;
                int rs = gk / C_;
                int ic = gk - rs * C_;
                int dr = rs / 3 - 1, dc = rs % 3 - 1;
                const float* xp = Bb + (size_t)ic * HW_;
#pragma unroll
                for (int i = 0; i < 4; i++) {
                    int n  = n0 + lane + 32 * i;          // coalesced 128B / warp instr
                    int h  = n / HWD, w = n - h * HWD;
                    int hh = h + dr,  ww = w + dc;
                    float v = 0.f;
                    if ((unsigned)hh < (unsigned)HWD && (unsigned)ww < (unsigned)HWD)
                        v = xp[hh * HWD + ww];
                    Bs[kk][lane + 32 * i] = v;
                }
            }
        }
        __syncthreads();
#pragma unroll
        for (int p = 0; p < KT; p++) {
            ull a2[6], b2[4];
            const ull* bp = (const ull*)&Bs[p][tx * 8];
#pragma unroll
            for (int j = 0; j < 4; j++) b2[j] = bp[j];
#pragma unroll
            for (int r = 0; r < 6; r++) a2[r] = pack2(As[p][ty * 6 + r]);
#pragma unroll
            for (int r = 0; r < 6; r++)
#pragma unroll
                for (int j = 0; j < 4; j++) ffma2(acc[r][j], a2[r], b2[j]);
        }
        __syncthreads();
    }
#pragma unroll
    for (int r = 0; r < 6; r++) {
        ull* cp = (ull*)(Cb + (size_t)(m0 + ty * 6 + r) * HW_ + n0 + tx * 8);
#pragma unroll
        for (int j = 0; j < 4; j++) cp[j] = acc[r][j];
    }
}

// ---------------- depthwise 3x3 SAME, groups = 384 ---------------------------
__global__ void dwconv3x3(const float* __restrict__ w) {
    size_t idx = (size_t)blockIdx.x * 256 + threadIdx.x;
    int pix = (int)(idx % HW_);
    size_t bc = idx / HW_;                 // b*384 + ch
    int ch = (int)(bc % CH2);
    int h = pix / HWD, x_ = pix - h * HWD;
    const float* wp = w + ch * 9;
    const float* ip = g_kv1 + bc * HW_;
    float s = 0.f;
#pragma unroll
    for (int r = 0; r < 3; r++) {
        int hh = h + r - 1;
        if ((unsigned)hh < (unsigned)HWD) {
#pragma unroll
            for (int c2 = 0; c2 < 3; c2++) {
                int ww = x_ + c2 - 1;
                if ((unsigned)ww < (unsigned)HWD)
                    s += wp[r * 3 + c2] * ip[hh * HWD + ww];
            }
        }
    }
    g_kv2[idx] = s;
}

// ---------------- Gram matrix q·kᵀ + fused sum-of-squares (split-K) ----------
__global__ void __launch_bounds__(1024)
gram_partial() {
    int bh = blockIdx.x, s = blockIdx.y;
    int b = bh / HEADS, h = bh % HEADS;
    int row = threadIdx.x >> 5;
    int col = threadIdx.x & 31;
    __shared__ float qs[32][33], ks[32][33];

    const float* qrow = g_q   + ((size_t)b * C_  + h * HD + row) * HW_;
    const float* krow = g_kv2 + ((size_t)b * CH2 + h * HD + row) * HW_;

    float acc = 0.f, aq = 0.f, ak = 0.f;
    int nbase = s * 2048;
    for (int it = 0; it < 64; it++) {
        int n = nbase + it * 32 + col;
        float qv = qrow[n];
        float kv = krow[n];
        qs[row][col] = qv;
        ks[row][col] = kv;
        aq += qv * qv;
        ak += kv * kv;
        __syncthreads();
#pragma unroll
        for (int t = 0; t < 32; t++)
            acc += qs[row][t] * ks[col][t];
        __syncthreads();
    }
    g_part[((size_t)(bh * NSPLIT + s)) * 1024 + row * 32 + col] = acc;
#pragma unroll
    for (int off = 16; off; off >>= 1) {
        aq += __shfl_xor_sync(0xffffffffu, aq, off);
        ak += __shfl_xor_sync(0xffffffffu, ak, off);
    }
    if (col == 0) {
        g_psq[(bh * NSPLIT + s) * 32 + row] = aq;
        g_psk[(bh * NSPLIT + s) * 32 + row] = ak;
    }
}

// ---------------- softmax + fused (proj @ attn) matrix build -----------------
__global__ void __launch_bounds__(256)
softmax_buildM(const float* __restrict__ proj_w,
               const float* __restrict__ temperature) {
    int bh = blockIdx.x;
    int b = bh / HEADS, h = bh % HEADS;
    int tid = threadIdx.x;
    __shared__ float att[32][32];
    __shared__ float invq[32], invk[32];

    for (int e = tid; e < 1024; e += 256) {
        float s = 0.f;
        for (int p = 0; p < NSPLIT; p++)
            s += g_part[((size_t)(bh * NSPLIT + p)) * 1024 + e];
        att[e >> 5][e & 31] = s;
    }
    if (tid < 32) {
        float sq = 0.f, sk = 0.f;
        for (int p = 0; p < NSPLIT; p++) {
            sq += g_psq[(bh * NSPLIT + p) * 32 + tid];
            sk += g_psk[(bh * NSPLIT + p) * 32 + tid];
        }
        invq[tid] = 1.f / fmaxf(sqrtf(sq), 1e-12f);
        invk[tid] = 1.f / fmaxf(sqrtf(sk), 1e-12f);
    }
    __syncthreads();

    float temp = temperature[h];
    for (int e = tid; e < 1024; e += 256) {
        int i = e >> 5, j = e & 31;
        att[i][j] = att[i][j] * invq[i] * invk[j] * temp;
    }
    __syncthreads();

    if (tid < 32) {
        int i = tid;
        float mx = -1e30f;
        for (int j = 0; j < 32; j++) mx = fmaxf(mx, att[i][j]);
        float sum = 0.f;
        for (int j = 0; j < 32; j++) { float e2 = __expf(att[i][j] - mx); att[i][j] = e2; sum += e2; }
        float inv = 1.f / sum;
        for (int j = 0; j < 32; j++) att[i][j] *= inv;
    }
    __syncthreads();

    // M[oc, d] = sum_c proj[oc, hbase+c] * att[c][d]  (stored K-major: [d][oc])
    for (int e = tid; e < C_ * HD; e += 256) {
        int oc = e >> 5;
        int d  = e & 31;
        float s = 0.f;
#pragma unroll
        for (int c = 0; c < 32; c++)
            s += proj_w[oc * C_ + h * HD + c] * att[c][d];
        g_M[((size_t)b * C_ + h * HD + d) * C_ + oc] = s;
    }
}

// ---------------- launch ------------------------------------------------------
extern "C" void kernel_launch(void* const* d_in, const int* in_sizes, int n_in,
                              void* d_out, int out_size) {
    const float* x      = (const float*)d_in[0];
    const float* y      = (const float*)d_in[1];
    const float* q_w    = (const float*)d_in[2];
    const float* kv_w   = (const float*)d_in[3];
    const float* kvdw_w = (const float*)d_in[4];
    const float* proj_w = (const float*)d_in[5];
    const float* temp   = (const float*)d_in[6];
    float* out = (float*)d_out;

    float *pAq, *pAkv, *pM, *pkv1, *pkv2, *pq;
    cudaGetSymbolAddress((void**)&pAq,  g_Aq);
    cudaGetSymbolAddress((void**)&pAkv, g_Akv);
    cudaGetSymbolAddress((void**)&pM,   g_M);
    cudaGetSymbolAddress((void**)&pkv1, g_kv1);
    cudaGetSymbolAddress((void**)&pkv2, g_kv2);
    cudaGetSymbolAddress((void**)&pq,   g_q);

    // 1. weight reorder
    prep_weights<<<(1728 * C_ + 255) / 256, 256>>>(q_w, kv_w);

    // 2. kv = 1x1 conv(y)
    sgemm96<false><<<dim3(HW_ / 128, CH2 / 96, B_), 256>>>(
        pAkv, 0LL, y, (long long)C_ * HW_, pkv1, (long long)CH2 * HW_, CH2, C_);

    // 3. depthwise 3x3
    dwconv3x3<<<(unsigned)(((size_t)B_ * CH2 * HW_) / 256), 256>>>(kvdw_w);

    // 4. q = 3x3 conv(x), implicit GEMM K=1728
    sgemm96<true><<<dim3(HW_ / 128, C_ / 96, B_), 256>>>(
        pAq, 0LL, x, (long long)C_ * HW_, pq, (long long)C_ * HW_, C_, 1728);

    // 5. Gram matrix + sumsq (split-K, deterministic)
    gram_partial<<<dim3(B_ * HEADS, NSPLIT), 1024>>>();

    // 6. softmax + fused proj@attn matrix
    softmax_buildM<<<B_ * HEADS, 256>>>(proj_w, temp);

    // 7. out = M @ v (fuses attn@v and the 1x1 projection)
    sgemm96<false><<<dim3(HW_ / 128, C_ / 96, B_), 256>>>(
        pM, (long long)C_ * C_,
        pkv2 + (size_t)C_ * HW_, (long long)CH2 * HW_,
        out, (long long)C_ * HW_, C_, C_);
}

// round 13
// speedup vs baseline: 1.4141x; 1.2512x over previous
#include <cuda_runtime.h>
#include <math.h>

// Problem constants
#define B_   4
#define C_   192
#define HWD  192          // spatial H = W = 192
#define HW_  36864        // 192*192
#define CH2  384          // 2*C
#define HEADS 6
#define HD    32          // head dim (C/heads)
#define NSPLIT 18         // split-K chunks for Gram matrix (36864/18 = 2048)
#define KT   16           // GEMM k-tile

typedef unsigned long long ull;

// ---------------- scratch (static device globals; no allocation) -------------
__device__ float g_kv1[(size_t)B_ * CH2 * HW_];   // 1x1 conv output (pre-depthwise)
__device__ float g_kv2[(size_t)B_ * CH2 * HW_];   // k (ch 0..191) | v (ch 192..383)
__device__ float g_q  [(size_t)B_ * C_  * HW_];   // q = 3x3 conv output
__device__ float g_Aq [1728 * C_];                // q weights, K-major [k][m], k=rs*192+ic
__device__ float g_Akv[C_ * CH2];                 // kv 1x1 weights, K-major [ic][oc]
__device__ float g_part[24 * NSPLIT * 1024];      // Gram partials [bh][split][32][32]
__device__ float g_psq [24 * NSPLIT * 32];        // sum(q^2) partials
__device__ float g_psk [24 * NSPLIT * 32];        // sum(k^2) partials
__device__ float g_M   [B_ * C_ * C_];            // fused (proj @ attn), K-major [b][d][oc]

// ---------------- packed f32x2 helpers ----------------------------------------
__device__ __forceinline__ ull pack2(float a) {
    ull r;
    asm("mov.b64 %0, {%1, %1};" : "=l"(r) : "r"(__float_as_uint(a)));
    return r;
}
__device__ __forceinline__ void ffma2(ull& acc, ull a, ull b) {
    asm("fma.rn.f32x2 %0, %1, %2, %0;" : "+l"(acc) : "l"(a), "l"(b));
}

// ---------------- weight reordering ------------------------------------------
__global__ void prep_weights(const float* __restrict__ qw,
                             const float* __restrict__ kvw) {
    int idx = blockIdx.x * blockDim.x + threadIdx.x;
    if (idx < 1728 * C_) {
        int k = idx / C_, m = idx % C_;          // k = rs*192 + ic
        int rs = k / C_, ic = k % C_;
        g_Aq[idx] = qw[(m * C_ + ic) * 9 + rs];  // qw OIHW [oc][ic][3][3]
    }
    if (idx < C_ * CH2) {
        int ic = idx / CH2, oc = idx % CH2;
        g_Akv[idx] = kvw[oc * C_ + ic];          // kvw [384][192][1][1]
    }
}

// ---------------- SGEMM 96x128xKT, 6x8 microtile, packed f32x2 ---------------
// C[m,n] = sum_k A[k][m] * B[k][n];  A is K-major (lda = M).
// Thread (ty,tx) covers m = m0+ty*6..+5, n = {n0+tx*4..+3, n0+64+tx*4..+3}.
// LDS.128 at 16B lane stride -> conflict-free fragment reads.
template<bool CONV>
__global__ void __launch_bounds__(256)
sgemm96(const float* __restrict__ A, long long A_bs,
        const float* __restrict__ Bsrc, long long B_bs,
        float* __restrict__ Cdst, long long C_bs,
        int M, int K) {
    const int b  = blockIdx.z;
    const int n0 = blockIdx.x * 128;
    const int m0 = blockIdx.y * 96;
    const float* Ab = A    + (size_t)b * A_bs;
    const float* Bb = Bsrc + (size_t)b * B_bs;
    float*       Cb = Cdst + (size_t)b * C_bs;

    __shared__ __align__(16) float As[KT][96];
    __shared__ __align__(16) float Bs[KT][128];

    const int tid  = threadIdx.x;
    const int ty   = tid >> 4, tx = tid & 15;    // 16x16 thread grid
    const int bk   = tid >> 5;                   // 0..7 (B-tile k row, +8 for 2nd)
    const int lane = tid & 31;

    ull acc[6][4];                               // [m-row][n-pair]; pairs 0,1 -> tx*4; 2,3 -> 64+tx*4
#pragma unroll
    for (int r = 0; r < 6; r++)
#pragma unroll
        for (int j = 0; j < 4; j++) acc[r][j] = 0ULL;

    for (int k0 = 0; k0 < K; k0 += KT) {
        // ---- A tile: 96*KT = 1536 elems / 256 thr = 6 each
#pragma unroll
        for (int i = 0; i < 6; i++) {
            int e = tid + i * 256;
            int kk = e / 96, mm = e - kk * 96;
            As[kk][mm] = Ab[(size_t)(k0 + kk) * M + m0 + mm];
        }
        // ---- B tile: 128*KT = 2048 elems / 256 thr = 8 each
        if (!CONV) {
#pragma unroll
            for (int i2 = 0; i2 < 2; i2++) {
                int kk = bk + 8 * i2;
                float4 v = *(const float4*)(Bb + (size_t)(k0 + kk) * HW_ + n0 + lane * 4);
                *(float4*)&Bs[kk][lane * 4] = v;
            }
        } else {
#pragma unroll
            for (int i2 = 0; i2 < 2; i2++) {
                int kk = bk + 8 * i2;
                int gk = k0 + kk;
                int rs = gk / C_;
                int ic = gk - rs * C_;
                int dr = rs / 3 - 1, dc = rs % 3 - 1;
                const float* xp = Bb + (size_t)ic * HW_;
#pragma unroll
                for (int i = 0; i < 4; i++) {
                    int n  = n0 + lane + 32 * i;          // coalesced 128B / warp instr
                    int h  = n / HWD, w = n - h * HWD;
                    int hh = h + dr,  ww = w + dc;
                    float v = 0.f;
                    if ((unsigned)hh < (unsigned)HWD && (unsigned)ww < (unsigned)HWD)
                        v = xp[hh * HWD + ww];
                    Bs[kk][lane + 32 * i] = v;
                }
            }
        }
        __syncthreads();
#pragma unroll
        for (int p = 0; p < KT; p++) {
            // B fragments: 2x LDS.128, conflict-free (16B lane stride)
            longlong2 lb0 = *(const longlong2*)&Bs[p][tx * 4];
            longlong2 lb1 = *(const longlong2*)&Bs[p][tx * 4 + 64];
            ull b2[4] = { (ull)lb0.x, (ull)lb0.y, (ull)lb1.x, (ull)lb1.y };
            // A fragment: 3x broadcast LDS.64 (ty*6 is even -> 8B aligned)
            float2 a01 = *(const float2*)&As[p][ty * 6];
            float2 a23 = *(const float2*)&As[p][ty * 6 + 2];
            float2 a45 = *(const float2*)&As[p][ty * 6 + 4];
            float av[6] = { a01.x, a01.y, a23.x, a23.y, a45.x, a45.y };
#pragma unroll
            for (int r = 0; r < 6; r++) {
                ull ar = pack2(av[r]);
#pragma unroll
                for (int j = 0; j < 4; j++) ffma2(acc[r][j], ar, b2[j]);
            }
        }
        __syncthreads();
    }
#pragma unroll
    for (int r = 0; r < 6; r++) {
        float* cp = Cb + (size_t)(m0 + ty * 6 + r) * HW_ + n0;
        longlong2 s0, s1;
        s0.x = (long long)acc[r][0]; s0.y = (long long)acc[r][1];
        s1.x = (long long)acc[r][2]; s1.y = (long long)acc[r][3];
        *(longlong2*)(cp + tx * 4)      = s0;
        *(longlong2*)(cp + 64 + tx * 4) = s1;
    }
}

// ---------------- depthwise 3x3 SAME, groups = 384 ---------------------------
__global__ void dwconv3x3(const float* __restrict__ w) {
    size_t idx = (size_t)blockIdx.x * 256 + threadIdx.x;
    int pix = (int)(idx % HW_);
    size_t bc = idx / HW_;                 // b*384 + ch
    int ch = (int)(bc % CH2);
    int h = pix / HWD, x_ = pix - h * HWD;
    const float* wp = w + ch * 9;
    const float* ip = g_kv1 + bc * HW_;
    float s = 0.f;
#pragma unroll
    for (int r = 0; r < 3; r++) {
        int hh = h + r - 1;
        if ((unsigned)hh < (unsigned)HWD) {
#pragma unroll
            for (int c2 = 0; c2 < 3; c2++) {
                int ww = x_ + c2 - 1;
                if ((unsigned)ww < (unsigned)HWD)
                    s += wp[r * 3 + c2] * ip[hh * HWD + ww];
            }
        }
    }
    g_kv2[idx] = s;
}

// ---------------- Gram matrix q·kᵀ + fused sum-of-squares (split-K) ----------
__global__ void __launch_bounds__(1024)
gram_partial() {
    int bh = blockIdx.x, s = blockIdx.y;
    int b = bh / HEADS, h = bh % HEADS;
    int row = threadIdx.x >> 5;
    int col = threadIdx.x & 31;
    __shared__ float qs[32][33], ks[32][33];

    const float* qrow = g_q   + ((size_t)b * C_  + h * HD + row) * HW_;
    const float* krow = g_kv2 + ((size_t)b * CH2 + h * HD + row) * HW_;

    float acc = 0.f, aq = 0.f, ak = 0.f;
    int nbase = s * 2048;
    for (int it = 0; it < 64; it++) {
        int n = nbase + it * 32 + col;
        float qv = qrow[n];
        float kv = krow[n];
        qs[row][col] = qv;
        ks[row][col] = kv;
        aq += qv * qv;
        ak += kv * kv;
        __syncthreads();
#pragma unroll
        for (int t = 0; t < 32; t++)
            acc += qs[row][t] * ks[col][t];
        __syncthreads();
    }
    g_part[((size_t)(bh * NSPLIT + s)) * 1024 + row * 32 + col] = acc;
#pragma unroll
    for (int off = 16; off; off >>= 1) {
        aq += __shfl_xor_sync(0xffffffffu, aq, off);
        ak += __shfl_xor_sync(0xffffffffu, ak, off);
    }
    if (col == 0) {
        g_psq[(bh * NSPLIT + s) * 32 + row] = aq;
        g_psk[(bh * NSPLIT + s) * 32 + row] = ak;
    }
}

// ---------------- softmax + fused (proj @ attn) matrix build -----------------
__global__ void __launch_bounds__(256)
softmax_buildM(const float* __restrict__ proj_w,
               const float* __restrict__ temperature) {
    int bh = blockIdx.x;
    int b = bh / HEADS, h = bh % HEADS;
    int tid = threadIdx.x;
    __shared__ float att[32][32];
    __shared__ float invq[32], invk[32];

    for (int e = tid; e < 1024; e += 256) {
        float s = 0.f;
        for (int p = 0; p < NSPLIT; p++)
            s += g_part[((size_t)(bh * NSPLIT + p)) * 1024 + e];
        att[e >> 5][e & 31] = s;
    }
    if (tid < 32) {
        float sq = 0.f, sk = 0.f;
        for (int p = 0; p < NSPLIT; p++) {
            sq += g_psq[(bh * NSPLIT + p) * 32 + tid];
            sk += g_psk[(bh * NSPLIT + p) * 32 + tid];
        }
        invq[tid] = 1.f / fmaxf(sqrtf(sq), 1e-12f);
        invk[tid] = 1.f / fmaxf(sqrtf(sk), 1e-12f);
    }
    __syncthreads();

    float temp = temperature[h];
    for (int e = tid; e < 1024; e += 256) {
        int i = e >> 5, j = e & 31;
        att[i][j] = att[i][j] * invq[i] * invk[j] * temp;
    }
    __syncthreads();

    if (tid < 32) {
        int i = tid;
        float mx = -1e30f;
        for (int j = 0; j < 32; j++) mx = fmaxf(mx, att[i][j]);
        float sum = 0.f;
        for (int j = 0; j < 32; j++) { float e2 = __expf(att[i][j] - mx); att[i][j] = e2; sum += e2; }
        float inv = 1.f / sum;
        for (int j = 0; j < 32; j++) att[i][j] *= inv;
    }
    __syncthreads();

    // M[oc, d] = sum_c proj[oc, hbase+c] * att[c][d]  (stored K-major: [d][oc])
    for (int e = tid; e < C_ * HD; e += 256) {
        int oc = e >> 5;
        int d  = e & 31;
        float s = 0.f;
#pragma unroll
        for (int c = 0; c < 32; c++)
            s += proj_w[oc * C_ + h * HD + c] * att[c][d];
        g_M[((size_t)b * C_ + h * HD + d) * C_ + oc] = s;
    }
}

// ---------------- launch ------------------------------------------------------
extern "C" void kernel_launch(void* const* d_in, const int* in_sizes, int n_in,
                              void* d_out, int out_size) {
    const float* x      = (const float*)d_in[0];
    const float* y      = (const float*)d_in[1];
    const float* q_w    = (const float*)d_in[2];
    const float* kv_w   = (const float*)d_in[3];
    const float* kvdw_w = (const float*)d_in[4];
    const float* proj_w = (const float*)d_in[5];
    const float* temp   = (const float*)d_in[6];
    float* out = (float*)d_out;

    float *pAq, *pAkv, *pM, *pkv1, *pkv2, *pq;
    cudaGetSymbolAddress((void**)&pAq,  g_Aq);
    cudaGetSymbolAddress((void**)&pAkv, g_Akv);
    cudaGetSymbolAddress((void**)&pM,   g_M);
    cudaGetSymbolAddress((void**)&pkv1, g_kv1);
    cudaGetSymbolAddress((void**)&pkv2, g_kv2);
    cudaGetSymbolAddress((void**)&pq,   g_q);

    // 1. weight reorder
    prep_weights<<<(1728 * C_ + 255) / 256, 256>>>(q_w, kv_w);

    // 2. kv = 1x1 conv(y)
    sgemm96<false><<<dim3(HW_ / 128, CH2 / 96, B_), 256>>>(
        pAkv, 0LL, y, (long long)C_ * HW_, pkv1, (long long)CH2 * HW_, CH2, C_);

    // 3. depthwise 3x3
    dwconv3x3<<<(unsigned)(((size_t)B_ * CH2 * HW_) / 256), 256>>>(kvdw_w);

    // 4. q = 3x3 conv(x), implicit GEMM K=1728
    sgemm96<true><<<dim3(HW_ / 128, C_ / 96, B_), 256>>>(
        pAq, 0LL, x, (long long)C_ * HW_, pq, (long long)C_ * HW_, C_, 1728);

    // 5. Gram matrix + sumsq (split-K, deterministic)
    gram_partial<<<dim3(B_ * HEADS, NSPLIT), 1024>>>();

    // 6. softmax + fused proj@attn matrix
    softmax_buildM<<<B_ * HEADS, 256>>>(proj_w, temp);

    // 7. out = M @ v (fuses attn@v and the 1x1 projection)
    sgemm96<false><<<dim3(HW_ / 128, C_ / 96, B_), 256>>>(
        pM, (long long)C_ * C_,
        pkv2 + (size_t)C_ * HW_, (long long)CH2 * HW_,
        out, (long long)C_ * HW_, C_, C_);
}

// round 14
// speedup vs baseline: 1.4178x; 1.0026x over previous
#include <cuda_runtime.h>
#include <math.h>

// Problem constants
#define B_   4
#define C_   192
#define HWD  192          // spatial H = W = 192
#define HW_  36864        // 192*192
#define CH2  384          // 2*C
#define HEADS 6
#define HD    32          // head dim (C/heads)
#define NSPLIT 18         // split-K chunks for Gram matrix (36864/18 = 2048)
#define KT   16           // GEMM k-tile

typedef unsigned long long ull;

// ---------------- scratch (static device globals; no allocation) -------------
__device__ float g_kv1[(size_t)B_ * CH2 * HW_];   // 1x1 conv output (pre-depthwise)
__device__ float g_kv2[(size_t)B_ * CH2 * HW_];   // k (ch 0..191) | v (ch 192..383)
__device__ float g_q  [(size_t)B_ * C_  * HW_];   // q = 3x3 conv output
__device__ float g_Aq [1728 * C_];                // q weights, K-major [k][m], k=rs*192+ic
__device__ float g_Akv[C_ * CH2];                 // kv 1x1 weights, K-major [ic][oc]
__device__ float g_part[24 * NSPLIT * 1024];      // Gram partials [bh][split][32][32]
__device__ float g_psq [24 * NSPLIT * 32];        // sum(q^2) partials
__device__ float g_psk [24 * NSPLIT * 32];        // sum(k^2) partials
__device__ float g_M   [B_ * C_ * C_];            // fused (proj @ attn), K-major [b][d][oc]

// ---------------- packed f32x2 helpers ----------------------------------------
__device__ __forceinline__ ull pack2(float a) {
    ull r;
    asm("mov.b64 %0, {%1, %1};" : "=l"(r) : "r"(__float_as_uint(a)));
    return r;
}
__device__ __forceinline__ void ffma2(ull& acc, ull a, ull b) {
    asm("fma.rn.f32x2 %0, %1, %2, %0;" : "+l"(acc) : "l"(a), "l"(b));
}

// ---------------- weight reordering ------------------------------------------
__global__ void prep_weights(const float* __restrict__ qw,
                             const float* __restrict__ kvw) {
    int idx = blockIdx.x * blockDim.x + threadIdx.x;
    if (idx < 1728 * C_) {
        int k = idx / C_, m = idx % C_;          // k = rs*192 + ic
        int rs = k / C_, ic = k % C_;
        g_Aq[idx] = qw[(m * C_ + ic) * 9 + rs];  // qw OIHW [oc][ic][3][3]
    }
    if (idx < C_ * CH2) {
        int ic = idx / CH2, oc = idx % CH2;
        g_Akv[idx] = kvw[oc * C_ + ic];          // kvw [384][192][1][1]
    }
}

// ---------------- SGEMM 96x128xKT, 6x8 microtile, packed f32x2 ---------------
// C[m,n] = sum_k A[k][m] * B[k][n];  A is K-major (lda = M).
// Thread (ty,tx) covers m = m0+ty*6..+5, n = {n0+tx*4..+3, n0+64+tx*4..+3}.
// LDS.128 at 16B lane stride -> conflict-free fragment reads.
template<bool CONV>
__global__ void __launch_bounds__(256)
sgemm96(const float* __restrict__ A, long long A_bs,
        const float* __restrict__ Bsrc, long long B_bs,
        float* __restrict__ Cdst, long long C_bs,
        int M, int K) {
    const int b  = blockIdx.z;
    const int n0 = blockIdx.x * 128;
    const int m0 = blockIdx.y * 96;
    const float* Ab = A    + (size_t)b * A_bs;
    const float* Bb = Bsrc + (size_t)b * B_bs;
    float*       Cb = Cdst + (size_t)b * C_bs;

    __shared__ __align__(16) float As[KT][96];
    __shared__ __align__(16) float Bs[KT][128];

    const int tid  = threadIdx.x;
    const int ty   = tid >> 4, tx = tid & 15;    // 16x16 thread grid
    const int bk   = tid >> 5;                   // 0..7 (B-tile k row, +8 for 2nd)
    const int lane = tid & 31;

    ull acc[6][4];                               // [m-row][n-pair]; pairs 0,1 -> tx*4; 2,3 -> 64+tx*4
#pragma unroll
    for (int r = 0; r < 6; r++)
#pragma unroll
        for (int j = 0; j < 4; j++) acc[r][j] = 0ULL;

    for (int k0 = 0; k0 < K; k0 += KT) {
        // ---- A tile: 96*KT = 1536 elems / 256 thr = 6 each
#pragma unroll
        for (int i = 0; i < 6; i++) {
            int e = tid + i * 256;
            int kk = e / 96, mm = e - kk * 96;
            As[kk][mm] = Ab[(size_t)(k0 + kk) * M + m0 + mm];
        }
        // ---- B tile: 128*KT = 2048 elems / 256 thr = 8 each
        if (!CONV) {
#pragma unroll
            for (int i2 = 0; i2 < 2; i2++) {
                int kk = bk + 8 * i2;
                float4 v = *(const float4*)(Bb + (size_t)(k0 + kk) * HW_ + n0 + lane * 4);
                *(float4*)&Bs[kk][lane * 4] = v;
            }
        } else {
#pragma unroll
            for (int i2 = 0; i2 < 2; i2++) {
                int kk = bk + 8 * i2;
                int gk = k0 + kk;
                int rs = gk / C_;
                int ic = gk - rs * C_;
                int dr = rs / 3 - 1, dc = rs % 3 - 1;
                const float* xp = Bb + (size_t)ic * HW_;
#pragma unroll
                for (int i = 0; i < 4; i++) {
                    int n  = n0 + lane + 32 * i;          // coalesced 128B / warp instr
                    int h  = n / HWD, w = n - h * HWD;
                    int hh = h + dr,  ww = w + dc;
                    float v = 0.f;
                    if ((unsigned)hh < (unsigned)HWD && (unsigned)ww < (unsigned)HWD)
                        v = xp[hh * HWD + ww];
                    Bs[kk][lane + 32 * i] = v;
                }
            }
        }
        __syncthreads();
#pragma unroll
        for (int p = 0; p < KT; p++) {
            // B fragments: 2x LDS.128, conflict-free (16B lane stride)
            longlong2 lb0 = *(const longlong2*)&Bs[p][tx * 4];
            longlong2 lb1 = *(const longlong2*)&Bs[p][tx * 4 + 64];
            ull b2[4] = { (ull)lb0.x, (ull)lb0.y, (ull)lb1.x, (ull)lb1.y };
            // A fragment: 3x broadcast LDS.64 (ty*6 is even -> 8B aligned)
            float2 a01 = *(const float2*)&As[p][ty * 6];
            float2 a23 = *(const float2*)&As[p][ty * 6 + 2];
            float2 a45 = *(const float2*)&As[p][ty * 6 + 4];
            float av[6] = { a01.x, a01.y, a23.x, a23.y, a45.x, a45.y };
#pragma unroll
            for (int r = 0; r < 6; r++) {
                ull ar = pack2(av[r]);
#pragma unroll
                for (int j = 0; j < 4; j++) ffma2(acc[r][j], ar, b2[j]);
            }
        }
        __syncthreads();
    }
#pragma unroll
    for (int r = 0; r < 6; r++) {
        float* cp = Cb + (size_t)(m0 + ty * 6 + r) * HW_ + n0;
        longlong2 s0, s1;
        s0.x = (long long)acc[r][0]; s0.y = (long long)acc[r][1];
        s1.x = (long long)acc[r][2]; s1.y = (long long)acc[r][3];
        *(longlong2*)(cp + tx * 4)      = s0;
        *(longlong2*)(cp + 64 + tx * 4) = s1;
    }
}

// ---------------- depthwise 3x3 SAME, groups = 384 ---------------------------
__global__ void dwconv3x3(const float* __restrict__ w) {
    size_t idx = (size_t)blockIdx.x * 256 + threadIdx.x;
    int pix = (int)(idx % HW_);
    size_t bc = idx / HW_;                 // b*384 + ch
    int ch = (int)(bc % CH2);
    int h = pix / HWD, x_ = pix - h * HWD;
    const float* wp = w + ch * 9;
    const float* ip = g_kv1 + bc * HW_;
    float s = 0.f;
#pragma unroll
    for (int r = 0; r < 3; r++) {
        int hh = h + r - 1;
        if ((unsigned)hh < (unsigned)HWD) {
#pragma unroll
            for (int c2 = 0; c2 < 3; c2++) {
                int ww = x_ + c2 - 1;
                if ((unsigned)ww < (unsigned)HWD)
                    s += wp[r * 3 + c2] * ip[hh * HWD + ww];
            }
        }
    }
    g_kv2[idx] = s;
}

// ---------------- Gram matrix q·kᵀ + fused sum-of-squares (split-K) ----------
__global__ void __launch_bounds__(1024)
gram_partial() {
    int bh = blockIdx.x, s = blockIdx.y;
    int b = bh / HEADS, h = bh % HEADS;
    int row = threadIdx.x >> 5;
    int col = threadIdx.x & 31;
    __shared__ float qs[32][33], ks[32][33];

    const float* qrow = g_q   + ((size_t)b * C_  + h * HD + row) * HW_;
    const float* krow = g_kv2 + ((size_t)b * CH2 + h * HD + row) * HW_;

    float acc = 0.f, aq = 0.f, ak = 0.f;
    int nbase = s * 2048;
    for (int it = 0; it < 64; it++) {
        int n = nbase + it * 32 + col;
        float qv = qrow[n];
        float kv = krow[n];
        qs[row][col] = qv;
        ks[row][col] = kv;
        aq += qv * qv;
        ak += kv * kv;
        __syncthreads();
#pragma unroll
        for (int t = 0; t < 32; t++)
            acc += qs[row][t] * ks[col][t];
        __syncthreads();
    }
    g_part[((size_t)(bh * NSPLIT + s)) * 1024 + row * 32 + col] = acc;
#pragma unroll
    for (int off = 16; off; off >>= 1) {
        aq += __shfl_xor_sync(0xffffffffu, aq, off);
        ak += __shfl_xor_sync(0xffffffffu, ak, off);
    }
    if (col == 0) {
        g_psq[(bh * NSPLIT + s) * 32 + row] = aq;
        g_psk[(bh * NSPLIT + s) * 32 + row] = ak;
    }
}

// ---------------- softmax + fused (proj @ attn) matrix build -----------------
__global__ void __launch_bounds__(256)
softmax_buildM(const float* __restrict__ proj_w,
               const float* __restrict__ temperature) {
    int bh = blockIdx.x;
    int b = bh / HEADS, h = bh % HEADS;
    int tid = threadIdx.x;
    __shared__ float att[32][32];
    __shared__ float invq[32], invk[32];

    for (int e = tid; e < 1024; e += 256) {
        float s = 0.f;
        for (int p = 0; p < NSPLIT; p++)
            s += g_part[((size_t)(bh * NSPLIT + p)) * 1024 + e];
        att[e >> 5][e & 31] = s;
    }
    if (tid < 32) {
        float sq = 0.f, sk = 0.f;
        for (int p = 0; p < NSPLIT; p++) {
            sq += g_psq[(bh * NSPLIT + p) * 32 + tid];
            sk += g_psk[(bh * NSPLIT + p) * 32 + tid];
        }
        invq[tid] = 1.f / fmaxf(sqrtf(sq), 1e-12f);
        invk[tid] = 1.f / fmaxf(sqrtf(sk), 1e-12f);
    }
    __syncthreads();

    float temp = temperature[h];
    for (int e = tid; e < 1024; e += 256) {
        int i = e >> 5, j = e & 31;
        att[i][j] = att[i][j] * invq[i] * invk[j] * temp;
    }
    __syncthreads();

    if (tid < 32) {
        int i = tid;
        float mx = -1e30f;
        for (int j = 0; j < 32; j++) mx = fmaxf(mx, att[i][j]);
        float sum = 0.f;
        for (int j = 0; j < 32; j++) { float e2 = __expf(att[i][j] - mx); att[i][j] = e2; sum += e2; }
        float inv = 1.f / sum;
        for (int j = 0; j < 32; j++) att[i][j] *= inv;
    }
    __syncthreads();

    // M[oc, d] = sum_c proj[oc, hbase+c] * att[c][d]  (stored K-major: [d][oc])
    for (int e = tid; e < C_ * HD; e += 256) {
        int oc = e >> 5;
        int d  = e & 31;
        float s = 0.f;
#pragma unroll
        for (int c = 0; c < 32; c++)
            s += proj_w[oc * C_ + h * HD + c] * att[c][d];
        g_M[((size_t)b * C_ + h * HD + d) * C_ + oc] = s;
    }
}

// ---------------- launch ------------------------------------------------------
extern "C" void kernel_launch(void* const* d_in, const int* in_sizes, int n_in,
                              void* d_out, int out_size) {
    const float* x      = (const float*)d_in[0];
    const float* y      = (const float*)d_in[1];
    const float* q_w    = (const float*)d_in[2];
    const float* kv_w   = (const float*)d_in[3];
    const float* kvdw_w = (const float*)d_in[4];
    const float* proj_w = (const float*)d_in[5];
    const float* temp   = (const float*)d_in[6];
    float* out = (float*)d_out;

    float *pAq, *pAkv, *pM, *pkv1, *pkv2, *pq;
    cudaGetSymbolAddress((void**)&pAq,  g_Aq);
    cudaGetSymbolAddress((void**)&pAkv, g_Akv);
    cudaGetSymbolAddress((void**)&pM,   g_M);
    cudaGetSymbolAddress((void**)&pkv1, g_kv1);
    cudaGetSymbolAddress((void**)&pkv2, g_kv2);
    cudaGetSymbolAddress((void**)&pq,   g_q);

    // 1. weight reorder
    prep_weights<<<(1728 * C_ + 255) / 256, 256>>>(q_w, kv_w);

    // 2. kv = 1x1 conv(y)
    sgemm96<false><<<dim3(HW_ / 128, CH2 / 96, B_), 256>>>(
        pAkv, 0LL, y, (long long)C_ * HW_, pkv1, (long long)CH2 * HW_, CH2, C_);

    // 3. depthwise 3x3
    dwconv3x3<<<(unsigned)(((size_t)B_ * CH2 * HW_) / 256), 256>>>(kvdw_w);

    // 4. q = 3x3 conv(x), implicit GEMM K=1728
    sgemm96<true><<<dim3(HW_ / 128, C_ / 96, B_), 256>>>(
        pAq, 0LL, x, (long long)C_ * HW_, pq, (long long)C_ * HW_, C_, 1728);

    // 5. Gram matrix + sumsq (split-K, deterministic)
    gram_partial<<<dim3(B_ * HEADS, NSPLIT), 1024>>>();

    // 6. softmax + fused proj@attn matrix
    softmax_buildM<<<B_ * HEADS, 256>>>(proj_w, temp);

    // 7. out = M @ v (fuses attn@v and the 1x1 projection)
    sgemm96<false><<<dim3(HW_ / 128, C_ / 96, B_), 256>>>(
        pM, (long long)C_ * C_,
        pkv2 + (size_t)C_ * HW_, (long long)CH2 * HW_,
        out, (long long)C_ * HW_, C_, C_);
}